// round 15
// baseline (speedup 1.0000x reference)
#include <cuda_runtime.h>
#include <cuda_fp16.h>
#include <cstdint>

// RecurTreeGen: 12-level Tree-LSTM reduction via warp-level fp16 mma.sync.
// P[m,640] = A[m,256] @ W, W single fp16.
// Levels 0-8: A single fp16 (1 term); levels 9-11: exact hi+lo (2 terms).
// 128-row CTAs, warp tile 32x80 (acc[2][10], 80 regs) -> 2 CTAs/SM;
// B half-resident in smem (5 LDS.128/warp/kt serve 20 HMMA — 2x B reuse),
// A via per-warp self-service 4-stage cp.async ring. Grid = (gy, m/128).

#define NLEVELS 12

// ---------------- device scratch (static; no allocation) ----------------
__device__ uint4 g_AfH[2][(size_t)8192 * 16 * 32];   // [buf][(mtG*16+kt)*32+lane]
__device__ uint4 g_AfL[2][(size_t)8192 * 16 * 32];
__device__ __align__(16) float g_cb[2][(size_t)131072 * 128];
__device__ uint2 g_Wf[40960];   // [(gy*16+kt)*640 + (pair*32+lane)*2 + half]

// ---------------- helpers ----------------
__device__ __forceinline__ uint32_t smem_u32(const void* p) {
    uint32_t a;
    asm("{ .reg .u64 t; cvta.to.shared.u64 t, %1; cvt.u32.u64 %0, t; }"
        : "=r"(a) : "l"(p));
    return a;
}
__device__ __forceinline__ void cp16(uint32_t d, const void* s) {
    asm volatile("cp.async.cg.shared.global [%0],[%1],16;" :: "r"(d), "l"(s) : "memory");
}
#define CP_COMMIT() asm volatile("cp.async.commit_group;" ::: "memory")
#define CP_WAIT3()  asm volatile("cp.async.wait_group 3;" ::: "memory")
#define CP_WAIT0()  asm volatile("cp.async.wait_group 0;" ::: "memory")

// exact fp16 hi/lo split of two floats, packed as half2 words
__device__ __forceinline__ void split2h(float x, float y, uint32_t& hi, uint32_t& lo) {
    __half hx = __float2half_rn(x), hy = __float2half_rn(y);
    float rx = x - __half2float(hx);
    float ry = y - __half2float(hy);
    __half lx = __float2half_rn(rx), ly = __float2half_rn(ry);
    __half2 h = __halves2half2(hx, hy), l = __halves2half2(lx, ly);
    hi = *reinterpret_cast<uint32_t*>(&h);
    lo = *reinterpret_cast<uint32_t*>(&l);
}
__device__ __forceinline__ uint32_t pack_h2(float x, float y) {
    __half2 h = __floats2half2_rn(x, y);
    return *reinterpret_cast<uint32_t*>(&h);
}
__device__ __forceinline__ void mma16816(float* d, const uint32_t* a, const uint32_t* b) {
    asm volatile(
        "mma.sync.aligned.m16n8k16.row.col.f32.f16.f16.f32 "
        "{%0,%1,%2,%3}, {%4,%5,%6,%7}, {%8,%9}, {%0,%1,%2,%3};"
        : "+f"(d[0]), "+f"(d[1]), "+f"(d[2]), "+f"(d[3])
        : "r"(a[0]), "r"(a[1]), "r"(a[2]), "r"(a[3]), "r"(b[0]), "r"(b[1]));
}

__device__ __forceinline__ float sigf(float x) {
    return 1.0f / (1.0f + __expf(-x));
}
__device__ __forceinline__ float tanhfast(float x) {
    return __fdividef(2.0f, 1.0f + __expf(-2.0f * x)) - 1.0f;
}
__device__ __forceinline__ void cell1(float pi, float po, float pu, float pf1, float pf2,
                                      float bi, float bo, float bu, float b1, float b2,
                                      float cl, float crv, float& h, float& c) {
    float iv = sigf(pi + bi), ov = sigf(po + bo), uv = tanhfast(pu + bu);
    float f1 = sigf(pf1 + b1), f2 = sigf(pf2 + b2);
    c = iv * uv + f1 * cl + f2 * crv;
    h = ov * tanhfast(c);
}

// ---------------- W pack: fp32 -> single fp16 B-frags, pair-interleaved ----------
__global__ void pack_w(const float* __restrict__ U_iou, const float* __restrict__ Uf_W) {
    int idx = blockIdx.x * 256 + threadIdx.x;   // < 40960
    int gy = idx / 10240;
    int rem = idx % 10240;
    int kt = rem / 640;
    int f = rem % 640;
    int nt = f >> 5;
    int lane = f & 31;
    int c = nt * 8 + (lane >> 2);
    int gate = c >> 5, feat = c & 31;
    int j = gy * 32 + feat;
    int k0 = kt * 16 + (lane & 3) * 2;

    float w0, w1, w2, w3;
    if (gate < 3) {
        w0 = U_iou[(k0 + 0) * 384 + gate * 128 + j];
        w1 = U_iou[(k0 + 1) * 384 + gate * 128 + j];
        w2 = U_iou[(k0 + 8) * 384 + gate * 128 + j];
        w3 = U_iou[(k0 + 9) * 384 + gate * 128 + j];
    } else {
        w0 = Uf_W[(k0 + 0) * 256 + (gate - 3) * 128 + j];
        w1 = Uf_W[(k0 + 1) * 256 + (gate - 3) * 128 + j];
        w2 = Uf_W[(k0 + 8) * 256 + (gate - 3) * 128 + j];
        w3 = Uf_W[(k0 + 9) * 256 + (gate - 3) * 128 + j];
    }
    uint2 v;
    v.x = pack_h2(w0, w1);
    v.y = pack_h2(w2, w3);

    int wn = nt / 10, i = nt % 10;
    int pair = wn * 5 + (i >> 1);
    g_Wf[(gy * 16 + kt) * 640 + (pair * 32 + lane) * 2 + (i & 1)] = v;
}

// ---------------- level-0 A convert: h_bot -> frag layout (hi only) ----------------
__global__ void conv_a(const float* __restrict__ hb) {
    int wid = threadIdx.x >> 5, lane = threadIdx.x & 31;
    int tile = blockIdx.x * 8 + wid;                 // < 131072 (mtG*16+kt)
    const float* base = hb + (size_t)(tile >> 4) * 16 * 256 + (tile & 15) * 16;
    int r = lane >> 2, kq = (lane & 3) * 2;
    float2 v00 = *(const float2*)(base + (r + 0) * 256 + kq + 0);
    float2 v10 = *(const float2*)(base + (r + 8) * 256 + kq + 0);
    float2 v01 = *(const float2*)(base + (r + 0) * 256 + kq + 8);
    float2 v11 = *(const float2*)(base + (r + 8) * 256 + kq + 8);
    uint4 hi;
    hi.x = pack_h2(v00.x, v00.y);
    hi.y = pack_h2(v10.x, v10.y);
    hi.z = pack_h2(v01.x, v01.y);
    hi.w = pack_h2(v11.x, v11.y);
    g_AfH[0][(size_t)tile * 32 + lane] = hi;
}

// ---------------- GEMM + fused cell ----------------
// Grid: (4, (m+127)/128); 256 threads; 8 warps: wm=wid>>1 (32 rows), wn=wid&1.
// SMEM: B resident [0,40960): [ktl(8)][pair(10)][lane(32)]x16B;
//       A ring [40960,...): [stage(4)][warp(8)][ASLOT] (hi t0|hi t1|lo t0|lo t1).
// Epilogue overlay: Ps 64x172 (44032) | sHi 8KB (44032) | sLo 8KB (52224).
template <int TERMS>
__global__ void __launch_bounds__(256, 2)
gemm_level(const float* __restrict__ c_bot,
           const float* __restrict__ b_iou, const float* __restrict__ Uf_b,
           float* __restrict__ out, int level, int m) {
    extern __shared__ char smem[];
    const uint32_t sb = smem_u32(smem);
    const int tid = threadIdx.x, wid = tid >> 5, lane = tid & 31;
    const int wm = wid >> 1, wn = wid & 1;
    const int gy = blockIdx.x, rb = blockIdx.y;
    const int rowbase = rb * 128;
    const bool last = (level == NLEVELS - 1);
    const bool need_lo = (level >= 8);
    const int rd = level & 1, wb = (level + 1) & 1;
    const uint4* __restrict__ AH = g_AfH[rd];
    const uint4* __restrict__ AL = g_AfL[rd];
    const float* Cin = (level == 0) ? c_bot : g_cb[(level + 1) & 1];

    constexpr int ASLOT = (TERMS == 2) ? 2048 : 1024;
    constexpr int ASTG = 8 * ASLOT;

    float acc[2][10][4];
#pragma unroll
    for (int t = 0; t < 2; t++)
#pragma unroll
        for (int i = 0; i < 10; i++)
#pragma unroll
            for (int q = 0; q < 4; q++) acc[t][i][q] = 0.0f;

    auto issueA = [&](int s, int kt) {
        uint32_t d = sb + 40960 + s * ASTG + wid * ASLOT + lane * 16;
#pragma unroll
        for (int t = 0; t < 2; t++) {
            size_t ai = ((size_t)(rb * 8 + wm * 2 + t) * 16 + kt) * 32 + lane;
            cp16(d + t * 512, AH + ai);
            if (TERMS == 2) cp16(d + 1024 + t * 512, AL + ai);
        }
    };
    auto loadB = [&](int kth) {
        const uint4* bsrc = (const uint4*)(g_Wf + ((size_t)gy * 16 + kth * 8) * 640);
#pragma unroll
        for (int t = 0; t < 10; t++)
            cp16(sb + (tid + t * 256) * 16, bsrc + tid + t * 256);
    };

    issueA(0, 0); CP_COMMIT();
    issueA(1, 1); CP_COMMIT();
    issueA(2, 2); CP_COMMIT();
    loadB(0);     CP_COMMIT();
    CP_WAIT0();
    __syncthreads();

#pragma unroll 1
    for (int kt = 0; kt < 16; kt++) {
        if (kt == 8) {
            __syncthreads();
            loadB(1); CP_COMMIT();
            CP_WAIT0();
            __syncthreads();
        }
        if (kt + 3 < 16) issueA((kt + 3) & 3, kt + 3);
        CP_COMMIT();
        CP_WAIT3();

        const char* aslot = smem + 40960 + (kt & 3) * ASTG + wid * ASLOT;
        uint4 AHf[2], ALf[2];
#pragma unroll
        for (int t = 0; t < 2; t++) {
            AHf[t] = *(const uint4*)(aslot + t * 512 + lane * 16);
            if (TERMS == 2)
                ALf[t] = *(const uint4*)(aslot + 1024 + t * 512 + lane * 16);
        }
        const char* bbase = smem + (((kt & 7) * 10 + wn * 5) * 32 + lane) * 16;
#pragma unroll
        for (int p = 0; p < 5; p++) {
            uint4 Bp = *(const uint4*)(bbase + p * 512);
            mma16816(acc[0][2 * p],     (const uint32_t*)&AHf[0], &Bp.x);
            mma16816(acc[0][2 * p + 1], (const uint32_t*)&AHf[0], &Bp.z);
            mma16816(acc[1][2 * p],     (const uint32_t*)&AHf[1], &Bp.x);
            mma16816(acc[1][2 * p + 1], (const uint32_t*)&AHf[1], &Bp.z);
            if (TERMS == 2) {
                mma16816(acc[0][2 * p],     (const uint32_t*)&ALf[0], &Bp.x);
                mma16816(acc[0][2 * p + 1], (const uint32_t*)&ALf[0], &Bp.z);
                mma16816(acc[1][2 * p],     (const uint32_t*)&ALf[1], &Bp.x);
                mma16816(acc[1][2 * p + 1], (const uint32_t*)&ALf[1], &Bp.z);
            }
        }
    }

    // --- epilogue, two 64-row halves (Ps overlay: 64 x 172 fp32) ---
    float* Ps = (float*)smem;
    uint32_t* sHi = (uint32_t*)(smem + 44032);
    uint32_t* sLo = (uint32_t*)(smem + 52224);

#pragma unroll
    for (int half = 0; half < 2; half++) {
        __syncthreads();
        if ((wm >> 1) == half) {
            const int prl = (wm & 1) * 32 + (lane >> 2);
            const int pcol = wn * 80 + (lane & 3) * 2;
#pragma unroll
            for (int t = 0; t < 2; t++)
#pragma unroll
                for (int i = 0; i < 10; i++) {
                    int rr0 = prl + t * 16;
                    int cc = pcol + i * 8;
                    *(float2*)&Ps[(rr0 + 0) * 172 + cc] =
                        make_float2(acc[t][i][0], acc[t][i][1]);
                    *(float2*)&Ps[(rr0 + 8) * 172 + cc] =
                        make_float2(acc[t][i][2], acc[t][i][3]);
                }
        }
        __syncthreads();
        if ((tid >> 7) == half) {
            const int r = tid >> 1, fh = tid & 1;
            const int rl = r & 63;
            const int R = rowbase + r;
            if (R < m) {
                const int j0 = gy * 32 + fh * 16;
                float hr[16];
#pragma unroll
                for (int q = 0; q < 4; q++) {
                    int cb = fh * 16 + q * 4;
                    float4 pi  = *(const float4*)&Ps[rl * 172 + 0 * 32 + cb];
                    float4 po  = *(const float4*)&Ps[rl * 172 + 1 * 32 + cb];
                    float4 pu  = *(const float4*)&Ps[rl * 172 + 2 * 32 + cb];
                    float4 pf1 = *(const float4*)&Ps[rl * 172 + 3 * 32 + cb];
                    float4 pf2 = *(const float4*)&Ps[rl * 172 + 4 * 32 + cb];
                    int j = j0 + q * 4;
                    float4 bi  = *(const float4*)(b_iou + 0 + j);
                    float4 bo  = *(const float4*)(b_iou + 128 + j);
                    float4 bu  = *(const float4*)(b_iou + 256 + j);
                    float4 bf1 = *(const float4*)(Uf_b + 0 + j);
                    float4 bf2 = *(const float4*)(Uf_b + 128 + j);
                    float4 cl  = *(const float4*)(Cin + (size_t)R * 256 + j);
                    float4 crv = *(const float4*)(Cin + (size_t)R * 256 + 128 + j);

                    float4 hv, cv;
                    cell1(pi.x, po.x, pu.x, pf1.x, pf2.x, bi.x, bo.x, bu.x,
                          bf1.x, bf2.x, cl.x, crv.x, hv.x, cv.x);
                    cell1(pi.y, po.y, pu.y, pf1.y, pf2.y, bi.y, bo.y, bu.y,
                          bf1.y, bf2.y, cl.y, crv.y, hv.y, cv.y);
                    cell1(pi.z, po.z, pu.z, pf1.z, pf2.z, bi.z, bo.z, bu.z,
                          bf1.z, bf2.z, cl.z, crv.z, hv.z, cv.z);
                    cell1(pi.w, po.w, pu.w, pf1.w, pf2.w, bi.w, bo.w, bu.w,
                          bf1.w, bf2.w, cl.w, crv.w, hv.w, cv.w);

                    hr[q * 4 + 0] = hv.x; hr[q * 4 + 1] = hv.y;
                    hr[q * 4 + 2] = hv.z; hr[q * 4 + 3] = hv.w;

                    if (last) {
                        *(float4*)(out + (size_t)R * 256 + j) = hv;
                        *(float4*)(out + (size_t)R * 256 + 128 + j) = cv;
                    } else {
                        *(float4*)(&g_cb[level & 1][(size_t)R * 128 + j]) = cv;
                    }
                }
                if (!last) {
                    const int mtl = r >> 5;
                    const int rr = (r >> 1) & 15;
                    const int ktl = (r & 1) * 2 + fh;
#pragma unroll
                    for (int p = 0; p < 8; p++) {
                        uint32_t h32, l32;
                        split2h(hr[2 * p], hr[2 * p + 1], h32, l32);
                        int idxu = ((mtl * 4 + ktl) * 32 + (rr & 7) * 4 + (p & 3)) * 4
                                 + (rr >> 3) + 2 * (p >> 2);
                        sHi[idxu] = h32;
                        if (need_lo) sLo[idxu] = l32;
                    }
                }
            }
        }
    }
    __syncthreads();
    if (!last) {
        uint4* dH = g_AfH[wb];
        uint4* dL = g_AfL[wb];
#pragma unroll
        for (int c0 = 0; c0 < 2; c0++) {
            int c = tid + c0 * 256;                 // < 512 uint4 units
            int mtl = c >> 7, ktl = (c >> 5) & 3, lu = c & 31;
            int ktg = (ktl >> 1) * 8 + gy * 2 + (ktl & 1);
            size_t di = ((size_t)(rb * 4 + mtl) * 16 + ktg) * 32 + lu;
            dH[di] = ((const uint4*)sHi)[c];
            if (need_lo) dL[di] = ((const uint4*)sLo)[c];
        }
    }
}

extern "C" void kernel_launch(void* const* d_in, const int* in_sizes, int n_in,
                              void* d_out, int out_size) {
    const float* h_bot = (const float*)d_in[0];
    const float* c_bot = (const float*)d_in[1];
    const float* U_iou = (const float*)d_in[2];
    const float* b_iou = (const float*)d_in[3];
    const float* Uf_W  = (const float*)d_in[4];
    const float* Uf_b  = (const float*)d_in[5];
    float* out = (float*)d_out;

    const int SMEM_T1 = 40960 + 4 * 8 * 1024;   // 73728
    const int SMEM_T2 = 40960 + 4 * 8 * 2048;   // 106496

    cudaFuncSetAttribute(gemm_level<1>, cudaFuncAttributeMaxDynamicSharedMemorySize,
                         SMEM_T1);
    cudaFuncSetAttribute(gemm_level<2>, cudaFuncAttributeMaxDynamicSharedMemorySize,
                         SMEM_T2);

    pack_w<<<160, 256>>>(U_iou, Uf_W);
    conv_a<<<16384, 256>>>(h_bot);

    int nstates = 262144;
    for (int l = 0; l < NLEVELS; l++) {
        int m = nstates >> 1;
        dim3 grid(4, (m + 127) / 128);
        if (l <= 8)
            gemm_level<1><<<grid, 256, SMEM_T1>>>(c_bot, b_iou, Uf_b, out, l, m);
        else
            gemm_level<2><<<grid, 256, SMEM_T2>>>(c_bot, b_iou, Uf_b, out, l, m);
        nstates = m;
    }
}

// round 16
// speedup vs baseline: 1.6127x; 1.6127x over previous
#include <cuda_runtime.h>
#include <cuda_fp16.h>
#include <cstdint>

// RecurTreeGen: 12-level Tree-LSTM reduction via warp-level fp16 mma.sync.
// P[m,640] = A[m,256] @ W, W single fp16.
// Levels 0-8: A single fp16 (1 term); levels 9-11: exact hi+lo (2 terms).
// 64-row CTAs, warp tile 16x80, 3 CTAs/SM (6 warps/SMSP — the proven config).
// B half-resident in smem (reload once at kt=8).
// A global->REGISTER direct (LDG software pipeline, distance 2) — no A smem
// ring, no per-kt cp.async/commit/wait. Grid = (gy, m/64).

#define NLEVELS 12
#define SMEM_BYTES 52224     // B 40960; epilogue overlay Ps 44032 + sHi/sLo 8192

// ---------------- device scratch (static; no allocation) ----------------
__device__ uint4 g_AfH[2][(size_t)8192 * 16 * 32];   // [buf][(mtG*16+kt)*32+lane]
__device__ uint4 g_AfL[2][(size_t)8192 * 16 * 32];
__device__ __align__(16) float g_cb[2][(size_t)131072 * 128];
__device__ uint2 g_Wf[40960];   // [(gy*16+kt)*640 + (pair*32+lane)*2 + half]

// ---------------- helpers ----------------
__device__ __forceinline__ uint32_t smem_u32(const void* p) {
    uint32_t a;
    asm("{ .reg .u64 t; cvta.to.shared.u64 t, %1; cvt.u32.u64 %0, t; }"
        : "=r"(a) : "l"(p));
    return a;
}
__device__ __forceinline__ void cp16(uint32_t d, const void* s) {
    asm volatile("cp.async.cg.shared.global [%0],[%1],16;" :: "r"(d), "l"(s) : "memory");
}
#define CP_COMMIT() asm volatile("cp.async.commit_group;" ::: "memory")
#define CP_WAIT0()  asm volatile("cp.async.wait_group 0;" ::: "memory")

// exact fp16 hi/lo split of two floats, packed as half2 words
__device__ __forceinline__ void split2h(float x, float y, uint32_t& hi, uint32_t& lo) {
    __half hx = __float2half_rn(x), hy = __float2half_rn(y);
    float rx = x - __half2float(hx);
    float ry = y - __half2float(hy);
    __half lx = __float2half_rn(rx), ly = __float2half_rn(ry);
    __half2 h = __halves2half2(hx, hy), l = __halves2half2(lx, ly);
    hi = *reinterpret_cast<uint32_t*>(&h);
    lo = *reinterpret_cast<uint32_t*>(&l);
}
__device__ __forceinline__ uint32_t pack_h2(float x, float y) {
    __half2 h = __floats2half2_rn(x, y);
    return *reinterpret_cast<uint32_t*>(&h);
}
__device__ __forceinline__ void mma16816(float* d, const uint32_t* a, const uint32_t* b) {
    asm volatile(
        "mma.sync.aligned.m16n8k16.row.col.f32.f16.f16.f32 "
        "{%0,%1,%2,%3}, {%4,%5,%6,%7}, {%8,%9}, {%0,%1,%2,%3};"
        : "+f"(d[0]), "+f"(d[1]), "+f"(d[2]), "+f"(d[3])
        : "r"(a[0]), "r"(a[1]), "r"(a[2]), "r"(a[3]), "r"(b[0]), "r"(b[1]));
}

__device__ __forceinline__ float sigf(float x) {
    return 1.0f / (1.0f + __expf(-x));
}
__device__ __forceinline__ float tanhfast(float x) {
    return __fdividef(2.0f, 1.0f + __expf(-2.0f * x)) - 1.0f;
}
__device__ __forceinline__ void cell1(float pi, float po, float pu, float pf1, float pf2,
                                      float bi, float bo, float bu, float b1, float b2,
                                      float cl, float crv, float& h, float& c) {
    float iv = sigf(pi + bi), ov = sigf(po + bo), uv = tanhfast(pu + bu);
    float f1 = sigf(pf1 + b1), f2 = sigf(pf2 + b2);
    c = iv * uv + f1 * cl + f2 * crv;
    h = ov * tanhfast(c);
}

// ---------------- W pack: fp32 -> single fp16 B-frags, pair-interleaved ----------
__global__ void pack_w(const float* __restrict__ U_iou, const float* __restrict__ Uf_W) {
    int idx = blockIdx.x * 256 + threadIdx.x;   // < 40960
    int gy = idx / 10240;
    int rem = idx % 10240;
    int kt = rem / 640;
    int f = rem % 640;
    int nt = f >> 5;
    int lane = f & 31;
    int c = nt * 8 + (lane >> 2);
    int gate = c >> 5, feat = c & 31;
    int j = gy * 32 + feat;
    int k0 = kt * 16 + (lane & 3) * 2;

    float w0, w1, w2, w3;
    if (gate < 3) {
        w0 = U_iou[(k0 + 0) * 384 + gate * 128 + j];
        w1 = U_iou[(k0 + 1) * 384 + gate * 128 + j];
        w2 = U_iou[(k0 + 8) * 384 + gate * 128 + j];
        w3 = U_iou[(k0 + 9) * 384 + gate * 128 + j];
    } else {
        w0 = Uf_W[(k0 + 0) * 256 + (gate - 3) * 128 + j];
        w1 = Uf_W[(k0 + 1) * 256 + (gate - 3) * 128 + j];
        w2 = Uf_W[(k0 + 8) * 256 + (gate - 3) * 128 + j];
        w3 = Uf_W[(k0 + 9) * 256 + (gate - 3) * 128 + j];
    }
    uint2 v;
    v.x = pack_h2(w0, w1);
    v.y = pack_h2(w2, w3);

    int wn = nt / 10, i = nt % 10;
    int pair = wn * 5 + (i >> 1);
    g_Wf[(gy * 16 + kt) * 640 + (pair * 32 + lane) * 2 + (i & 1)] = v;
}

// ---------------- level-0 A convert: h_bot -> frag layout (hi only) ----------------
__global__ void conv_a(const float* __restrict__ hb) {
    int wid = threadIdx.x >> 5, lane = threadIdx.x & 31;
    int tile = blockIdx.x * 8 + wid;                 // < 131072 (mtG*16+kt)
    const float* base = hb + (size_t)(tile >> 4) * 16 * 256 + (tile & 15) * 16;
    int r = lane >> 2, kq = (lane & 3) * 2;
    float2 v00 = *(const float2*)(base + (r + 0) * 256 + kq + 0);
    float2 v10 = *(const float2*)(base + (r + 8) * 256 + kq + 0);
    float2 v01 = *(const float2*)(base + (r + 0) * 256 + kq + 8);
    float2 v11 = *(const float2*)(base + (r + 8) * 256 + kq + 8);
    uint4 hi;
    hi.x = pack_h2(v00.x, v00.y);
    hi.y = pack_h2(v10.x, v10.y);
    hi.z = pack_h2(v01.x, v01.y);
    hi.w = pack_h2(v11.x, v11.y);
    g_AfH[0][(size_t)tile * 32 + lane] = hi;
}

// ---------------- GEMM + fused cell ----------------
// Grid: (4, m/64); 256 threads (8 warps: wm=wid>>1 in 0..3 over 64 rows, wn=wid&1).
// SMEM: B resident [0,40960): [ktl(8)][pair(10)][lane(32)]x16B.
// A is read straight into registers (LDG pipeline, distance 2, unroll x2).
template <int TERMS>
__global__ void __launch_bounds__(256, 3)
gemm_level(const float* __restrict__ c_bot,
           const float* __restrict__ b_iou, const float* __restrict__ Uf_b,
           float* __restrict__ out, int level, int m) {
    extern __shared__ char smem[];
    const uint32_t sb = smem_u32(smem);
    const int tid = threadIdx.x, wid = tid >> 5, lane = tid & 31;
    const int wm = wid >> 1, wn = wid & 1;
    const int gy = blockIdx.x, rb = blockIdx.y;
    const int rowbase = rb * 64;
    const bool last = (level == NLEVELS - 1);
    const bool need_lo = (level >= 8);
    const int rd = level & 1, wb = (level + 1) & 1;
    const float* Cin = (level == 0) ? c_bot : g_cb[(level + 1) & 1];

    // per-warp A stream: stride 32 uint4 per kt
    const uint4* __restrict__ aPH =
        g_AfH[rd] + ((size_t)(rb * 4 + wm) * 16) * 32 + lane;
    const uint4* __restrict__ aPL =
        g_AfL[rd] + ((size_t)(rb * 4 + wm) * 16) * 32 + lane;

    float acc[10][4];
#pragma unroll
    for (int i = 0; i < 10; i++)
#pragma unroll
        for (int q = 0; q < 4; q++) acc[i][q] = 0.0f;

    auto loadB = [&](int kth) {
        const uint4* bsrc = (const uint4*)(g_Wf + ((size_t)gy * 16 + kth * 8) * 640);
#pragma unroll
        for (int t = 0; t < 10; t++)
            cp16(sb + (tid + t * 256) * 16, bsrc + tid + t * 256);
    };

    // A register pipeline: two buffers, distance 2
    uint4 aH0 = aPH[0 * 32], aH1 = aPH[1 * 32];
    uint4 aL0, aL1;
    if (TERMS == 2) { aL0 = aPL[0 * 32]; aL1 = aPL[1 * 32]; }

    loadB(0); CP_COMMIT();
    CP_WAIT0();
    __syncthreads();

#pragma unroll 1
    for (int kt2 = 0; kt2 < 8; kt2++) {
        if (kt2 == 4) {
            __syncthreads();
            loadB(1); CP_COMMIT();
            CP_WAIT0();
            __syncthreads();
        }
        const int kt = kt2 * 2;
        // ---- even kt ----
        {
            uint4 AHf = aH0, ALf;
            if (TERMS == 2) ALf = aL0;
            if (kt + 2 < 16) {
                aH0 = aPH[(kt + 2) * 32];
                if (TERMS == 2) aL0 = aPL[(kt + 2) * 32];
            }
            const char* bbase = smem + (((kt & 7) * 10 + wn * 5) * 32 + lane) * 16;
#pragma unroll
            for (int p = 0; p < 5; p++) {
                uint4 Bp = *(const uint4*)(bbase + p * 512);
                mma16816(acc[2 * p],     (const uint32_t*)&AHf, &Bp.x);
                mma16816(acc[2 * p + 1], (const uint32_t*)&AHf, &Bp.z);
                if (TERMS == 2) {
                    mma16816(acc[2 * p],     (const uint32_t*)&ALf, &Bp.x);
                    mma16816(acc[2 * p + 1], (const uint32_t*)&ALf, &Bp.z);
                }
            }
        }
        // ---- odd kt ----
        {
            uint4 AHf = aH1, ALf;
            if (TERMS == 2) ALf = aL1;
            if (kt + 3 < 16) {
                aH1 = aPH[(kt + 3) * 32];
                if (TERMS == 2) aL1 = aPL[(kt + 3) * 32];
            }
            const char* bbase = smem + ((((kt + 1) & 7) * 10 + wn * 5) * 32 + lane) * 16;
#pragma unroll
            for (int p = 0; p < 5; p++) {
                uint4 Bp = *(const uint4*)(bbase + p * 512);
                mma16816(acc[2 * p],     (const uint32_t*)&AHf, &Bp.x);
                mma16816(acc[2 * p + 1], (const uint32_t*)&AHf, &Bp.z);
                if (TERMS == 2) {
                    mma16816(acc[2 * p],     (const uint32_t*)&ALf, &Bp.x);
                    mma16816(acc[2 * p + 1], (const uint32_t*)&ALf, &Bp.z);
                }
            }
        }
    }
    __syncthreads();

    // --- stage preacts: Ps[64][172] fp32 (overlays the dead B smem) ---
    float* Ps = (float*)smem;
    uint32_t* sHi = (uint32_t*)(smem + 44032);
    uint32_t* sLo = (uint32_t*)(smem + 48128);
    {
        const int prow = wm * 16 + (lane >> 2);
        const int pcol = wn * 80 + (lane & 3) * 2;
#pragma unroll
        for (int i = 0; i < 10; i++) {
            *(float2*)&Ps[(prow + 0) * 172 + pcol + i * 8] =
                make_float2(acc[i][0], acc[i][1]);
            *(float2*)&Ps[(prow + 8) * 172 + pcol + i * 8] =
                make_float2(acc[i][2], acc[i][3]);
        }
    }
    __syncthreads();

    // --- fused LSTM cell: thread = (row r, 8-feature group fh) ---
    {
        const int r = tid >> 2, fh = tid & 3;
        const int R = rowbase + r;
        const int j0 = gy * 32 + fh * 8;
        float hr[8];
#pragma unroll
        for (int q = 0; q < 2; q++) {
            const int cb = fh * 8 + q * 4;
            float4 pi  = *(const float4*)&Ps[r * 172 + 0 * 32 + cb];
            float4 po  = *(const float4*)&Ps[r * 172 + 1 * 32 + cb];
            float4 pu  = *(const float4*)&Ps[r * 172 + 2 * 32 + cb];
            float4 pf1 = *(const float4*)&Ps[r * 172 + 3 * 32 + cb];
            float4 pf2 = *(const float4*)&Ps[r * 172 + 4 * 32 + cb];
            const int j = j0 + q * 4;
            float4 bi  = *(const float4*)(b_iou + 0 + j);
            float4 bo  = *(const float4*)(b_iou + 128 + j);
            float4 bu  = *(const float4*)(b_iou + 256 + j);
            float4 bf1 = *(const float4*)(Uf_b + 0 + j);
            float4 bf2 = *(const float4*)(Uf_b + 128 + j);
            float4 cl  = *(const float4*)(Cin + (size_t)R * 256 + j);
            float4 crv = *(const float4*)(Cin + (size_t)R * 256 + 128 + j);

            float4 hv, cv;
            cell1(pi.x, po.x, pu.x, pf1.x, pf2.x, bi.x, bo.x, bu.x,
                  bf1.x, bf2.x, cl.x, crv.x, hv.x, cv.x);
            cell1(pi.y, po.y, pu.y, pf1.y, pf2.y, bi.y, bo.y, bu.y,
                  bf1.y, bf2.y, cl.y, crv.y, hv.y, cv.y);
            cell1(pi.z, po.z, pu.z, pf1.z, pf2.z, bi.z, bo.z, bu.z,
                  bf1.z, bf2.z, cl.z, crv.z, hv.z, cv.z);
            cell1(pi.w, po.w, pu.w, pf1.w, pf2.w, bi.w, bo.w, bu.w,
                  bf1.w, bf2.w, cl.w, crv.w, hv.w, cv.w);

            hr[q * 4 + 0] = hv.x; hr[q * 4 + 1] = hv.y;
            hr[q * 4 + 2] = hv.z; hr[q * 4 + 3] = hv.w;

            if (last) {
                *(float4*)(out + (size_t)R * 256 + j) = hv;
                *(float4*)(out + (size_t)R * 256 + 128 + j) = cv;
            } else {
                *(float4*)(&g_cb[level & 1][(size_t)R * 128 + j]) = cv;
            }
        }
        if (!last) {
            // h -> next-level A-fragment staging in smem
            const int mtl = r >> 5;                 // 0..1 (16 next-rows each)
            const int rr = (r >> 1) & 15;           // next-level row in tile
            const int ktl = (r & 1) * 2 + (fh >> 1);
#pragma unroll
            for (int p = 0; p < 4; p++) {
                uint32_t h32, l32;
                split2h(hr[2 * p], hr[2 * p + 1], h32, l32);
                int idxu = ((mtl * 4 + ktl) * 32 + (rr & 7) * 4 + p) * 4
                         + (rr >> 3) + 2 * (fh & 1);
                sHi[idxu] = h32;
                if (need_lo) sLo[idxu] = l32;
            }
        }
    }
    __syncthreads();
    if (!last) {
        uint4* dH = g_AfH[wb];
        uint4* dL = g_AfL[wb];
        const int c = tid;                           // 256 uint4 units
        const int mtl = c >> 7, ktl = (c >> 5) & 3, lu = c & 31;
        const int ktg = (ktl >> 1) * 8 + gy * 2 + (ktl & 1);
        const size_t di = ((size_t)(rb * 2 + mtl) * 16 + ktg) * 32 + lu;
        dH[di] = ((const uint4*)sHi)[c];
        if (need_lo) dL[di] = ((const uint4*)sLo)[c];
    }
}

extern "C" void kernel_launch(void* const* d_in, const int* in_sizes, int n_in,
                              void* d_out, int out_size) {
    const float* h_bot = (const float*)d_in[0];
    const float* c_bot = (const float*)d_in[1];
    const float* U_iou = (const float*)d_in[2];
    const float* b_iou = (const float*)d_in[3];
    const float* Uf_W  = (const float*)d_in[4];
    const float* Uf_b  = (const float*)d_in[5];
    float* out = (float*)d_out;

    cudaFuncSetAttribute(gemm_level<1>, cudaFuncAttributeMaxDynamicSharedMemorySize,
                         SMEM_BYTES);
    cudaFuncSetAttribute(gemm_level<2>, cudaFuncAttributeMaxDynamicSharedMemorySize,
                         SMEM_BYTES);

    pack_w<<<160, 256>>>(U_iou, Uf_W);
    conv_a<<<16384, 256>>>(h_bot);

    int nstates = 262144;
    for (int l = 0; l < NLEVELS; l++) {
        int m = nstates >> 1;
        dim3 grid(4, m / 64);
        if (l <= 8)
            gemm_level<1><<<grid, 256, SMEM_BYTES>>>(c_bot, b_iou, Uf_b, out, l, m);
        else
            gemm_level<2><<<grid, 256, SMEM_BYTES>>>(c_bot, b_iou, Uf_b, out, l, m);
        nstates = m;
    }
}